// round 3
// baseline (speedup 1.0000x reference)
#include <cuda_runtime.h>
#include <cuda_bf16.h>

#define NNODES 50000
#define NEDGES 800000
#define D_IN   128
#define D_H    192
#define D_K    64
#define NB     64
#define HID_DIM 256
#define OUT_DIM 10

// Scratch (static device globals; allocation is forbidden).
__device__ float g_H[NNODES * D_H];     // pre-aggregation features (x@W concat)
__device__ float g_AGG[NNODES * D_H];   // aggregation target (both layers)
__device__ float g_POOL[NB * D_H];      // pooled per-graph sums
__device__ float g_HID[NB * HID_DIM];   // MLP hidden

// ---------------------------------------------------------------------------
// Zero-fill helpers
// ---------------------------------------------------------------------------
__global__ void zero_agg_kernel() {
    const int i = blockIdx.x * blockDim.x + threadIdx.x;
    const int nvec = NNODES * D_H / 4;
    if (i < nvec) reinterpret_cast<float4*>(g_AGG)[i] = make_float4(0.f, 0.f, 0.f, 0.f);
}

__global__ void zero_pool_kernel() {
    const int i = blockIdx.x * blockDim.x + threadIdx.x;
    if (i < NB * D_H) g_POOL[i] = 0.f;
}

// ---------------------------------------------------------------------------
// Fused concat-GEMM: H[n, 0:192] = X[n,:] @ [W0|W1|W2] + [b0|b1|b2]
// Block: 192 threads (one output column each), TILE=16 nodes per block.
// SRC=0: read X pointer. SRC=1: read g_AGG (with relu folded into the load).
// ---------------------------------------------------------------------------
template <int DIN, bool RELU_IN, int SRC>
__global__ void __launch_bounds__(192) gemm_concat_kernel(
    const float* __restrict__ X,
    const float* __restrict__ W0, const float* __restrict__ b0,
    const float* __restrict__ W1, const float* __restrict__ b1,
    const float* __restrict__ W2, const float* __restrict__ b2)
{
    constexpr int TILE = 16;
    __shared__ __align__(16) float xs[TILE * DIN];

    const int tid   = threadIdx.x;
    const int node0 = blockIdx.x * TILE;

    const float* __restrict__ src = (SRC == 0) ? X : (const float*)g_AGG;

    // cooperative load of input tile (float4), zero-fill out-of-range nodes
    {
        float4* xs4 = reinterpret_cast<float4*>(xs);
        const int nvec = TILE * DIN / 4;
        for (int idx = tid; idx < nvec; idx += 192) {
            int node = idx / (DIN / 4);
            int kv   = idx % (DIN / 4);
            float4 v = make_float4(0.f, 0.f, 0.f, 0.f);
            int gn = node0 + node;
            if (gn < NNODES) {
                v = reinterpret_cast<const float4*>(src + (size_t)gn * DIN)[kv];
                if (RELU_IN) {
                    v.x = fmaxf(v.x, 0.f); v.y = fmaxf(v.y, 0.f);
                    v.z = fmaxf(v.z, 0.f); v.w = fmaxf(v.w, 0.f);
                }
            }
            xs4[idx] = v;
        }
    }
    __syncthreads();

    const int grp = tid >> 6;          // which hom-kernel (0..2)
    const int cc  = tid & 63;          // column within kernel
    const float* __restrict__ Wsel = (grp == 0) ? W0 : (grp == 1 ? W1 : W2);
    const float* __restrict__ bsel = (grp == 0) ? b0 : (grp == 1 ? b1 : b2);

    float acc[TILE];
    const float bias = bsel[cc];
#pragma unroll
    for (int i = 0; i < TILE; i++) acc[i] = bias;

    for (int k = 0; k < DIN; k += 4) {
        float w0 = Wsel[(k + 0) * D_K + cc];
        float w1 = Wsel[(k + 1) * D_K + cc];
        float w2 = Wsel[(k + 2) * D_K + cc];
        float w3 = Wsel[(k + 3) * D_K + cc];
#pragma unroll
        for (int i = 0; i < TILE; i++) {
            float4 xv = *reinterpret_cast<const float4*>(&xs[i * DIN + k]);
            acc[i] += xv.x * w0 + xv.y * w1 + xv.z * w2 + xv.w * w3;
        }
    }

#pragma unroll
    for (int i = 0; i < TILE; i++) {
        int gn = node0 + i;
        if (gn < NNODES) g_H[(size_t)gn * D_H + tid] = acc[i];
    }
}

// ---------------------------------------------------------------------------
// Edge scatter: AGG[dst, coff:coff+64] += H[src, coff:coff+64]
// 64 threads per edge, one scalar float each, plain atomicAdd.
// gridDim.y selects mapping 0..2 (column offset 0/64/128).
// ---------------------------------------------------------------------------
__global__ void __launch_bounds__(256) scatter_kernel(
    const int* __restrict__ m0, const int* __restrict__ m1,
    const int* __restrict__ m2)
{
    const int* __restrict__ m =
        (blockIdx.y == 0) ? m0 : (blockIdx.y == 1 ? m1 : m2);
    const int coff = blockIdx.y * D_K;

    const int tid = threadIdx.x;
    const int e   = blockIdx.x * 4 + (tid >> 6);   // 4 edges per block
    const int l   = tid & 63;                      // column lane
    if (e >= NEDGES) return;

    const int dst = m[e];
    const int src = m[NEDGES + e];

    const float v = g_H[(size_t)src * D_H + coff + l];
    atomicAdd(&g_AGG[(size_t)dst * D_H + coff + l], v);
}

// ---------------------------------------------------------------------------
// Pooling: POOL[batch_idx[n], c] += relu(AGG[n, c]).
// batch_idx is sorted -> per-segment register accumulation, atomic on change.
// ---------------------------------------------------------------------------
__global__ void __launch_bounds__(192) pool_kernel(
    const int* __restrict__ batch_idx)
{
    constexpr int CHUNK = 128;
    __shared__ int sb[CHUNK];

    const int tid   = threadIdx.x;
    const int node0 = blockIdx.x * CHUNK;

    for (int j = tid; j < CHUNK; j += 192) {
        int n = node0 + j;
        sb[j] = (n < NNODES) ? batch_idx[n] : -1;
    }
    __syncthreads();

    int   cur = -1;
    float acc = 0.f;
    for (int j = 0; j < CHUNK; j++) {
        int b = sb[j];
        if (b < 0) break;
        if (b != cur) {
            if (cur >= 0) atomicAdd(&g_POOL[cur * D_H + tid], acc);
            cur = b;
            acc = 0.f;
        }
        acc += fmaxf(g_AGG[(size_t)(node0 + j) * D_H + tid], 0.f);
    }
    if (cur >= 0) atomicAdd(&g_POOL[cur * D_H + tid], acc);
}

// ---------------------------------------------------------------------------
// MLP head
// ---------------------------------------------------------------------------
__global__ void __launch_bounds__(HID_DIM) mlp1_kernel(
    const float* __restrict__ A1, const float* __restrict__ ba1)
{
    __shared__ float sp[D_H];
    const int b = blockIdx.x;
    const int t = threadIdx.x;
    for (int k = t; k < D_H; k += HID_DIM) sp[k] = g_POOL[b * D_H + k];
    __syncthreads();

    float acc = ba1[t];
    for (int k = 0; k < D_H; k++) acc += sp[k] * A1[k * HID_DIM + t];
    g_HID[b * HID_DIM + t] = fmaxf(acc, 0.f);
}

__global__ void __launch_bounds__(NB * OUT_DIM) mlp2_kernel(
    const float* __restrict__ A2, const float* __restrict__ ba2,
    float* __restrict__ OUT)
{
    const int t = threadIdx.x;          // 0..639
    const int b = t / OUT_DIM;
    const int o = t % OUT_DIM;
    float acc = ba2[o];
    for (int k = 0; k < HID_DIM; k++)
        acc += g_HID[b * HID_DIM + k] * A2[k * OUT_DIM + o];
    OUT[b * OUT_DIM + o] = acc;
}

// ---------------------------------------------------------------------------
extern "C" void kernel_launch(void* const* d_in, const int* in_sizes, int n_in,
                              void* d_out, int out_size)
{
    const float* x         = (const float*)d_in[0];
    const int*   map00     = (const int*)d_in[1];
    const int*   map01     = (const int*)d_in[2];
    const int*   map02     = (const int*)d_in[3];
    const int*   map10     = (const int*)d_in[4];
    const int*   map11     = (const int*)d_in[5];
    const int*   map12     = (const int*)d_in[6];
    const int*   batch_idx = (const int*)d_in[7];
    // d_in[8] = batch_size (compile-time NB)
    const float* W00 = (const float*)d_in[9];
    const float* b00 = (const float*)d_in[10];
    const float* W01 = (const float*)d_in[11];
    const float* b01 = (const float*)d_in[12];
    const float* W02 = (const float*)d_in[13];
    const float* b02 = (const float*)d_in[14];
    const float* W10 = (const float*)d_in[15];
    const float* b10 = (const float*)d_in[16];
    const float* W11 = (const float*)d_in[17];
    const float* b11 = (const float*)d_in[18];
    const float* W12 = (const float*)d_in[19];
    const float* b12 = (const float*)d_in[20];
    const float* A1  = (const float*)d_in[21];
    const float* ba1 = (const float*)d_in[22];
    const float* A2  = (const float*)d_in[23];
    const float* ba2 = (const float*)d_in[24];
    float* out = (float*)d_out;

    const int gemm_blocks    = (NNODES + 15) / 16;
    const int scatter_blocks = (NEDGES + 3) / 4;
    const int pool_blocks    = (NNODES + 127) / 128;
    const int zero_blocks    = (NNODES * D_H / 4 + 255) / 256;

    // ---- layer 0 ----
    gemm_concat_kernel<D_IN, false, 0><<<gemm_blocks, 192>>>(
        x, W00, b00, W01, b01, W02, b02);
    zero_agg_kernel<<<zero_blocks, 256>>>();
    scatter_kernel<<<dim3(scatter_blocks, 3), 256>>>(map00, map01, map02);

    // ---- layer 1 (relu folded into GEMM input load) ----
    gemm_concat_kernel<D_H, true, 1><<<gemm_blocks, 192>>>(
        nullptr, W10, b10, W11, b11, W12, b12);
    zero_agg_kernel<<<zero_blocks, 256>>>();
    scatter_kernel<<<dim3(scatter_blocks, 3), 256>>>(map10, map11, map12);

    // ---- pooling (relu folded into load) ----
    zero_pool_kernel<<<(NB * D_H + 255) / 256, 256>>>();
    pool_kernel<<<pool_blocks, 192>>>(batch_idx);

    // ---- MLP head ----
    mlp1_kernel<<<NB, HID_DIM>>>(A1, ba1);
    mlp2_kernel<<<1, NB * OUT_DIM>>>(A2, ba2, out);
}

// round 4
// speedup vs baseline: 2.1284x; 2.1284x over previous
#include <cuda_runtime.h>
#include <cuda_bf16.h>

#define NNODES 50000
#define NEDGES 800000
#define D_IN   128
#define D_H    192
#define D_K    64
#define NB     64
#define HID_DIM 256
#define OUT_DIM 10

// Scratch (static device globals; allocation is forbidden).
__device__ float g_H[NNODES * D_H];     // pre-aggregation features (x@W concat)
__device__ float g_AGG[NNODES * D_H];   // aggregation target (both layers)
__device__ float g_POOL[NB * D_H];      // pooled per-graph sums
__device__ float g_HID[NB * HID_DIM];   // MLP hidden

// ---------------------------------------------------------------------------
// Zero-fill helpers
// ---------------------------------------------------------------------------
__global__ void zero_agg_kernel() {
    const int i = blockIdx.x * blockDim.x + threadIdx.x;
    const int nvec = NNODES * D_H / 4;
    if (i < nvec) reinterpret_cast<float4*>(g_AGG)[i] = make_float4(0.f, 0.f, 0.f, 0.f);
}

__global__ void zero_pool_kernel() {
    const int i = blockIdx.x * blockDim.x + threadIdx.x;
    if (i < NB * D_H) g_POOL[i] = 0.f;
}

// ---------------------------------------------------------------------------
// Fused concat-GEMM: H[n, 0:192] = X[n,:] @ [W0|W1|W2] + [b0|b1|b2]
// Block: 96 threads; thread t computes output columns t and t+96 for
// TILE=16 nodes -> each smem float4 load feeds 8 FFMAs (was 4).
// SRC=0: read X pointer. SRC=1: read g_AGG (relu folded into the load).
// ---------------------------------------------------------------------------
template <int DIN, bool RELU_IN, int SRC>
__global__ void __launch_bounds__(96) gemm_concat_kernel(
    const float* __restrict__ X,
    const float* __restrict__ W0, const float* __restrict__ b0,
    const float* __restrict__ W1, const float* __restrict__ b1,
    const float* __restrict__ W2, const float* __restrict__ b2)
{
    constexpr int TILE = 16;
    __shared__ __align__(16) float xs[TILE * DIN];

    const int tid   = threadIdx.x;       // 0..95
    const int node0 = blockIdx.x * TILE;

    const float* __restrict__ src = (SRC == 0) ? X : (const float*)g_AGG;

    // cooperative load of input tile (float4), zero-fill out-of-range nodes
    {
        float4* xs4 = reinterpret_cast<float4*>(xs);
        const int nvec = TILE * DIN / 4;
        for (int idx = tid; idx < nvec; idx += 96) {
            int node = idx / (DIN / 4);
            int kv   = idx % (DIN / 4);
            float4 v = make_float4(0.f, 0.f, 0.f, 0.f);
            int gn = node0 + node;
            if (gn < NNODES) {
                v = reinterpret_cast<const float4*>(src + (size_t)gn * DIN)[kv];
                if (RELU_IN) {
                    v.x = fmaxf(v.x, 0.f); v.y = fmaxf(v.y, 0.f);
                    v.z = fmaxf(v.z, 0.f); v.w = fmaxf(v.w, 0.f);
                }
            }
            xs4[idx] = v;
        }
    }
    __syncthreads();

    // two output columns per thread: c0 = tid, c1 = tid + 96
    const int c0 = tid;
    const int c1 = tid + 96;
    const int g0 = c0 >> 6, g1 = c1 >> 6;          // hom-kernel index 0..2
    const float* __restrict__ Wa = (g0 == 0) ? W0 : W1;
    const float* __restrict__ ba = (g0 == 0) ? b0 : b1;
    const float* __restrict__ Wb = (g1 == 1) ? W1 : W2;
    const float* __restrict__ bb = (g1 == 1) ? b1 : b2;
    const int ca = c0 & 63, cb = c1 & 63;

    float acc0[TILE], acc1[TILE];
    const float bias0 = ba[ca];
    const float bias1 = bb[cb];
#pragma unroll
    for (int i = 0; i < TILE; i++) { acc0[i] = bias0; acc1[i] = bias1; }

    for (int k = 0; k < DIN; k += 4) {
        float wa0 = Wa[(k + 0) * D_K + ca];
        float wa1 = Wa[(k + 1) * D_K + ca];
        float wa2 = Wa[(k + 2) * D_K + ca];
        float wa3 = Wa[(k + 3) * D_K + ca];
        float wb0 = Wb[(k + 0) * D_K + cb];
        float wb1 = Wb[(k + 1) * D_K + cb];
        float wb2 = Wb[(k + 2) * D_K + cb];
        float wb3 = Wb[(k + 3) * D_K + cb];
#pragma unroll
        for (int i = 0; i < TILE; i++) {
            float4 xv = *reinterpret_cast<const float4*>(&xs[i * DIN + k]);
            acc0[i] += xv.x * wa0 + xv.y * wa1 + xv.z * wa2 + xv.w * wa3;
            acc1[i] += xv.x * wb0 + xv.y * wb1 + xv.z * wb2 + xv.w * wb3;
        }
    }

#pragma unroll
    for (int i = 0; i < TILE; i++) {
        int gn = node0 + i;
        if (gn < NNODES) {
            g_H[(size_t)gn * D_H + c0] = acc0[i];
            g_H[(size_t)gn * D_H + c1] = acc1[i];
        }
    }
}

// ---------------------------------------------------------------------------
// Edge scatter: AGG[dst, coff:coff+64] += H[src, coff:coff+64]
// 16 threads per edge, float4 gather + red.global.add.v4.f32 scatter.
// gridDim.y selects mapping 0..2 (column offset 0/64/128).
// ---------------------------------------------------------------------------
__device__ __forceinline__ void red_add_v4(float* p, float4 v) {
    asm volatile("red.global.add.v4.f32 [%0], {%1, %2, %3, %4};"
                 :: "l"(p), "f"(v.x), "f"(v.y), "f"(v.z), "f"(v.w)
                 : "memory");
}

__global__ void __launch_bounds__(256) scatter_kernel(
    const int* __restrict__ m0, const int* __restrict__ m1,
    const int* __restrict__ m2)
{
    const int* __restrict__ m =
        (blockIdx.y == 0) ? m0 : (blockIdx.y == 1 ? m1 : m2);
    const int coff = blockIdx.y * D_K;

    const int tid = threadIdx.x;
    const int e   = blockIdx.x * 16 + (tid >> 4);  // 16 edges per block
    const int l   = tid & 15;                      // float4 lane
    if (e >= NEDGES) return;

    const int dst = m[e];
    const int src = m[NEDGES + e];

    const float4 v = *reinterpret_cast<const float4*>(
        g_H + (size_t)src * D_H + coff + l * 4);
    red_add_v4(g_AGG + (size_t)dst * D_H + coff + l * 4, v);
}

// ---------------------------------------------------------------------------
// Pooling: POOL[batch_idx[n], c] += relu(AGG[n, c]).
// batch_idx is sorted -> per-segment register accumulation, atomic on change.
// ---------------------------------------------------------------------------
__global__ void __launch_bounds__(192) pool_kernel(
    const int* __restrict__ batch_idx)
{
    constexpr int CHUNK = 128;
    __shared__ int sb[CHUNK];

    const int tid   = threadIdx.x;
    const int node0 = blockIdx.x * CHUNK;

    for (int j = tid; j < CHUNK; j += 192) {
        int n = node0 + j;
        sb[j] = (n < NNODES) ? batch_idx[n] : -1;
    }
    __syncthreads();

    int   cur = -1;
    float acc = 0.f;
    for (int j = 0; j < CHUNK; j++) {
        int b = sb[j];
        if (b < 0) break;
        if (b != cur) {
            if (cur >= 0) atomicAdd(&g_POOL[cur * D_H + tid], acc);
            cur = b;
            acc = 0.f;
        }
        acc += fmaxf(g_AGG[(size_t)(node0 + j) * D_H + tid], 0.f);
    }
    if (cur >= 0) atomicAdd(&g_POOL[cur * D_H + tid], acc);
}

// ---------------------------------------------------------------------------
// MLP head
// ---------------------------------------------------------------------------
__global__ void __launch_bounds__(HID_DIM) mlp1_kernel(
    const float* __restrict__ A1, const float* __restrict__ ba1)
{
    __shared__ float sp[D_H];
    const int b = blockIdx.x;
    const int t = threadIdx.x;
    for (int k = t; k < D_H; k += HID_DIM) sp[k] = g_POOL[b * D_H + k];
    __syncthreads();

    float acc = ba1[t];
    for (int k = 0; k < D_H; k++) acc += sp[k] * A1[k * HID_DIM + t];
    g_HID[b * HID_DIM + t] = fmaxf(acc, 0.f);
}

__global__ void __launch_bounds__(NB * OUT_DIM) mlp2_kernel(
    const float* __restrict__ A2, const float* __restrict__ ba2,
    float* __restrict__ OUT)
{
    const int t = threadIdx.x;          // 0..639
    const int b = t / OUT_DIM;
    const int o = t % OUT_DIM;
    float acc = ba2[o];
    for (int k = 0; k < HID_DIM; k++)
        acc += g_HID[b * HID_DIM + k] * A2[k * OUT_DIM + o];
    OUT[b * OUT_DIM + o] = acc;
}

// ---------------------------------------------------------------------------
extern "C" void kernel_launch(void* const* d_in, const int* in_sizes, int n_in,
                              void* d_out, int out_size)
{
    const float* x         = (const float*)d_in[0];
    const int*   map00     = (const int*)d_in[1];
    const int*   map01     = (const int*)d_in[2];
    const int*   map02     = (const int*)d_in[3];
    const int*   map10     = (const int*)d_in[4];
    const int*   map11     = (const int*)d_in[5];
    const int*   map12     = (const int*)d_in[6];
    const int*   batch_idx = (const int*)d_in[7];
    // d_in[8] = batch_size (compile-time NB)
    const float* W00 = (const float*)d_in[9];
    const float* b00 = (const float*)d_in[10];
    const float* W01 = (const float*)d_in[11];
    const float* b01 = (const float*)d_in[12];
    const float* W02 = (const float*)d_in[13];
    const float* b02 = (const float*)d_in[14];
    const float* W10 = (const float*)d_in[15];
    const float* b10 = (const float*)d_in[16];
    const float* W11 = (const float*)d_in[17];
    const float* b11 = (const float*)d_in[18];
    const float* W12 = (const float*)d_in[19];
    const float* b12 = (const float*)d_in[20];
    const float* A1  = (const float*)d_in[21];
    const float* ba1 = (const float*)d_in[22];
    const float* A2  = (const float*)d_in[23];
    const float* ba2 = (const float*)d_in[24];
    float* out = (float*)d_out;

    const int gemm_blocks    = (NNODES + 15) / 16;
    const int scatter_blocks = (NEDGES + 15) / 16;
    const int pool_blocks    = (NNODES + 127) / 128;
    const int zero_blocks    = (NNODES * D_H / 4 + 255) / 256;

    // ---- layer 0 ----
    gemm_concat_kernel<D_IN, false, 0><<<gemm_blocks, 96>>>(
        x, W00, b00, W01, b01, W02, b02);
    zero_agg_kernel<<<zero_blocks, 256>>>();
    scatter_kernel<<<dim3(scatter_blocks, 3), 256>>>(map00, map01, map02);

    // ---- layer 1 (relu folded into GEMM input load) ----
    gemm_concat_kernel<D_H, true, 1><<<gemm_blocks, 96>>>(
        nullptr, W10, b10, W11, b11, W12, b12);
    zero_agg_kernel<<<zero_blocks, 256>>>();
    scatter_kernel<<<dim3(scatter_blocks, 3), 256>>>(map10, map11, map12);

    // ---- pooling (relu folded into load) ----
    zero_pool_kernel<<<(NB * D_H + 255) / 256, 256>>>();
    pool_kernel<<<pool_blocks, 192>>>(batch_idx);

    // ---- MLP head ----
    mlp1_kernel<<<NB, HID_DIM>>>(A1, ba1);
    mlp2_kernel<<<1, NB * OUT_DIM>>>(A2, ba2, out);
}

// round 5
// speedup vs baseline: 3.1262x; 1.4688x over previous
#include <cuda_runtime.h>
#include <cuda_fp16.h>

#define NNODES 50000
#define NEDGES 800000
#define D_IN   128
#define D_H    192
#define D_K    64
#define NB     64
#define HID_DIM 256
#define OUT_DIM 10

// Scratch (static device globals; allocation is forbidden).
// H and AGG are fp16 (halves red-op count in the scatter).
__device__ __align__(16) __half g_H[NNODES * D_H];
__device__ __align__(16) __half g_AGG[NNODES * D_H];
__device__ float g_POOL[NB * D_H];
__device__ float g_HID[NB * HID_DIM];

// ---------------------------------------------------------------------------
// Zero-fill helpers
// ---------------------------------------------------------------------------
__global__ void zero_agg_kernel() {
    const int i = blockIdx.x * blockDim.x + threadIdx.x;
    const int nvec = NNODES * D_H / 8;     // 16-byte chunks of half
    if (i < nvec)
        reinterpret_cast<uint4*>(g_AGG)[i] = make_uint4(0u, 0u, 0u, 0u);
}

__global__ void zero_pool_kernel() {
    const int i = blockIdx.x * blockDim.x + threadIdx.x;
    if (i < NB * D_H) g_POOL[i] = 0.f;
}

// ---------------------------------------------------------------------------
// Fused concat-GEMM: H[n, 0:192] = in[n,:] @ [W0|W1|W2] + [b0|b1|b2]  (fp16 out)
// Block: 96 threads; thread t computes adjacent output columns 2t, 2t+1
// for TILE=16 nodes. SRC=0: fp32 X input. SRC=1: fp16 AGG input with relu.
// ---------------------------------------------------------------------------
template <int DIN, int SRC>
__global__ void __launch_bounds__(96) gemm_concat_kernel(
    const float* __restrict__ X,
    const float* __restrict__ W0, const float* __restrict__ b0,
    const float* __restrict__ W1, const float* __restrict__ b1,
    const float* __restrict__ W2, const float* __restrict__ b2)
{
    constexpr int TILE = 16;
    __shared__ __align__(16) float xs[TILE * DIN];

    const int tid   = threadIdx.x;       // 0..95
    const int node0 = blockIdx.x * TILE;

    // cooperative load of input tile into smem (fp32), zero-fill OOR nodes
    if (SRC == 0) {
        float4* xs4 = reinterpret_cast<float4*>(xs);
        const int nvec = TILE * DIN / 4;
        for (int idx = tid; idx < nvec; idx += 96) {
            int node = idx / (DIN / 4);
            int kv   = idx % (DIN / 4);
            float4 v = make_float4(0.f, 0.f, 0.f, 0.f);
            int gn = node0 + node;
            if (gn < NNODES)
                v = reinterpret_cast<const float4*>(X + (size_t)gn * DIN)[kv];
            xs4[idx] = v;
        }
    } else {
        // fp16 AGG input, relu folded into conversion; 8 halves per chunk
        const int nchunk = TILE * DIN / 8;
        for (int idx = tid; idx < nchunk; idx += 96) {
            int node = idx / (DIN / 8);
            int kc   = idx % (DIN / 8);
            float f[8];
            int gn = node0 + node;
            if (gn < NNODES) {
                uint4 raw = *reinterpret_cast<const uint4*>(
                    g_AGG + (size_t)gn * DIN + kc * 8);
                const __half2* h2 = reinterpret_cast<const __half2*>(&raw);
#pragma unroll
                for (int j = 0; j < 4; j++) {
                    float2 fv = __half22float2(h2[j]);
                    f[2*j]   = fmaxf(fv.x, 0.f);
                    f[2*j+1] = fmaxf(fv.y, 0.f);
                }
            } else {
#pragma unroll
                for (int j = 0; j < 8; j++) f[j] = 0.f;
            }
            float* dst = &xs[node * DIN + kc * 8];
#pragma unroll
            for (int j = 0; j < 8; j++) dst[j] = f[j];
        }
    }
    __syncthreads();

    // adjacent output columns: c0 = 2*tid, c1 = 2*tid+1 (same hom-kernel)
    const int c0  = 2 * tid;
    const int grp = tid / 32;            // hom-kernel index 0..2
    const float* __restrict__ Wsel = (grp == 0) ? W0 : (grp == 1 ? W1 : W2);
    const float* __restrict__ bsel = (grp == 0) ? b0 : (grp == 1 ? b1 : b2);
    const int ca = c0 & 63;              // even column within kernel

    float acc0[TILE], acc1[TILE];
    const float2 bias = *reinterpret_cast<const float2*>(bsel + ca);
#pragma unroll
    for (int i = 0; i < TILE; i++) { acc0[i] = bias.x; acc1[i] = bias.y; }

    for (int k = 0; k < DIN; k += 4) {
        float2 w0 = *reinterpret_cast<const float2*>(Wsel + (k + 0) * D_K + ca);
        float2 w1 = *reinterpret_cast<const float2*>(Wsel + (k + 1) * D_K + ca);
        float2 w2 = *reinterpret_cast<const float2*>(Wsel + (k + 2) * D_K + ca);
        float2 w3 = *reinterpret_cast<const float2*>(Wsel + (k + 3) * D_K + ca);
#pragma unroll
        for (int i = 0; i < TILE; i++) {
            float4 xv = *reinterpret_cast<const float4*>(&xs[i * DIN + k]);
            acc0[i] += xv.x * w0.x + xv.y * w1.x + xv.z * w2.x + xv.w * w3.x;
            acc1[i] += xv.x * w0.y + xv.y * w1.y + xv.z * w2.y + xv.w * w3.y;
        }
    }

#pragma unroll
    for (int i = 0; i < TILE; i++) {
        int gn = node0 + i;
        if (gn < NNODES) {
            __half2 h = __floats2half2_rn(acc0[i], acc1[i]);
            *reinterpret_cast<__half2*>(g_H + (size_t)gn * D_H + c0) = h;
        }
    }
}

// ---------------------------------------------------------------------------
// Edge scatter: AGG[dst, coff:coff+64] += H[src, coff:coff+64]   (fp16)
// 8 threads per edge; each covers 16 bytes = 8 halves via one
// red.global.add.noftz.v4.f16x2.
// ---------------------------------------------------------------------------
__device__ __forceinline__ void red_add_v4_f16x2(__half* p, uint4 v) {
    asm volatile("red.global.add.noftz.v4.f16x2 [%0], {%1, %2, %3, %4};"
                 :: "l"(p), "r"(v.x), "r"(v.y), "r"(v.z), "r"(v.w)
                 : "memory");
}

__global__ void __launch_bounds__(256) scatter_kernel(
    const int* __restrict__ m0, const int* __restrict__ m1,
    const int* __restrict__ m2)
{
    const int* __restrict__ m =
        (blockIdx.y == 0) ? m0 : (blockIdx.y == 1 ? m1 : m2);
    const int coff = blockIdx.y * D_K;   // half-element column offset

    const int tid = threadIdx.x;
    const int e   = blockIdx.x * 32 + (tid >> 3);  // 32 edges per block
    const int l   = tid & 7;                       // 16-byte lane
    if (e >= NEDGES) return;

    const int dst = m[e];
    const int src = m[NEDGES + e];

    const uint4 v = *reinterpret_cast<const uint4*>(
        g_H + (size_t)src * D_H + coff + l * 8);
    red_add_v4_f16x2(g_AGG + (size_t)dst * D_H + coff + l * 8, v);
}

// ---------------------------------------------------------------------------
// Pooling: POOL[batch_idx[n], c] += relu(AGG[n, c]).   (AGG fp16, POOL fp32)
// batch_idx is sorted -> per-segment register accumulation, atomic on change.
// ---------------------------------------------------------------------------
__global__ void __launch_bounds__(192) pool_kernel(
    const int* __restrict__ batch_idx)
{
    constexpr int CHUNK = 128;
    __shared__ int sb[CHUNK];

    const int tid   = threadIdx.x;
    const int node0 = blockIdx.x * CHUNK;

    for (int j = tid; j < CHUNK; j += 192) {
        int n = node0 + j;
        sb[j] = (n < NNODES) ? batch_idx[n] : -1;
    }
    __syncthreads();

    int   cur = -1;
    float acc = 0.f;
    for (int j = 0; j < CHUNK; j++) {
        int b = sb[j];
        if (b < 0) break;
        if (b != cur) {
            if (cur >= 0) atomicAdd(&g_POOL[cur * D_H + tid], acc);
            cur = b;
            acc = 0.f;
        }
        float v = __half2float(g_AGG[(size_t)(node0 + j) * D_H + tid]);
        acc += fmaxf(v, 0.f);
    }
    if (cur >= 0) atomicAdd(&g_POOL[cur * D_H + tid], acc);
}

// ---------------------------------------------------------------------------
// MLP head
// ---------------------------------------------------------------------------
__global__ void __launch_bounds__(HID_DIM) mlp1_kernel(
    const float* __restrict__ A1, const float* __restrict__ ba1)
{
    __shared__ float sp[D_H];
    const int b = blockIdx.x;
    const int t = threadIdx.x;
    for (int k = t; k < D_H; k += HID_DIM) sp[k] = g_POOL[b * D_H + k];
    __syncthreads();

    float acc = ba1[t];
    for (int k = 0; k < D_H; k++) acc += sp[k] * A1[k * HID_DIM + t];
    g_HID[b * HID_DIM + t] = fmaxf(acc, 0.f);
}

__global__ void __launch_bounds__(NB * OUT_DIM) mlp2_kernel(
    const float* __restrict__ A2, const float* __restrict__ ba2,
    float* __restrict__ OUT)
{
    const int t = threadIdx.x;          // 0..639
    const int b = t / OUT_DIM;
    const int o = t % OUT_DIM;
    float acc = ba2[o];
    for (int k = 0; k < HID_DIM; k++)
        acc += g_HID[b * HID_DIM + k] * A2[k * OUT_DIM + o];
    OUT[b * OUT_DIM + o] = acc;
}

// ---------------------------------------------------------------------------
extern "C" void kernel_launch(void* const* d_in, const int* in_sizes, int n_in,
                              void* d_out, int out_size)
{
    const float* x         = (const float*)d_in[0];
    const int*   map00     = (const int*)d_in[1];
    const int*   map01     = (const int*)d_in[2];
    const int*   map02     = (const int*)d_in[3];
    const int*   map10     = (const int*)d_in[4];
    const int*   map11     = (const int*)d_in[5];
    const int*   map12     = (const int*)d_in[6];
    const int*   batch_idx = (const int*)d_in[7];
    // d_in[8] = batch_size (compile-time NB)
    const float* W00 = (const float*)d_in[9];
    const float* b00 = (const float*)d_in[10];
    const float* W01 = (const float*)d_in[11];
    const float* b01 = (const float*)d_in[12];
    const float* W02 = (const float*)d_in[13];
    const float* b02 = (const float*)d_in[14];
    const float* W10 = (const float*)d_in[15];
    const float* b10 = (const float*)d_in[16];
    const float* W11 = (const float*)d_in[17];
    const float* b11 = (const float*)d_in[18];
    const float* W12 = (const float*)d_in[19];
    const float* b12 = (const float*)d_in[20];
    const float* A1  = (const float*)d_in[21];
    const float* ba1 = (const float*)d_in[22];
    const float* A2  = (const float*)d_in[23];
    const float* ba2 = (const float*)d_in[24];
    float* out = (float*)d_out;

    const int gemm_blocks    = (NNODES + 15) / 16;
    const int scatter_blocks = (NEDGES + 31) / 32;
    const int pool_blocks    = (NNODES + 127) / 128;
    const int zero_blocks    = (NNODES * D_H / 8 + 255) / 256;

    // ---- layer 0 ----
    gemm_concat_kernel<D_IN, 0><<<gemm_blocks, 96>>>(
        x, W00, b00, W01, b01, W02, b02);
    zero_agg_kernel<<<zero_blocks, 256>>>();
    scatter_kernel<<<dim3(scatter_blocks, 3), 256>>>(map00, map01, map02);

    // ---- layer 1 (relu folded into GEMM input load) ----
    gemm_concat_kernel<D_H, 1><<<gemm_blocks, 96>>>(
        nullptr, W10, b10, W11, b11, W12, b12);
    zero_agg_kernel<<<zero_blocks, 256>>>();
    scatter_kernel<<<dim3(scatter_blocks, 3), 256>>>(map10, map11, map12);

    // ---- pooling (relu folded into load) ----
    zero_pool_kernel<<<(NB * D_H + 255) / 256, 256>>>();
    pool_kernel<<<pool_blocks, 192>>>(batch_idx);

    // ---- MLP head ----
    mlp1_kernel<<<NB, HID_DIM>>>(A1, ba1);
    mlp2_kernel<<<1, NB * OUT_DIM>>>(A2, ba2, out);
}

// round 8
// speedup vs baseline: 3.5818x; 1.1458x over previous
#include <cuda_runtime.h>
#include <cuda_fp16.h>
#include <cstdint>

using std::uint32_t;

#define NNODES 50000
#define NEDGES 800000
#define D_IN   128
#define D_H    192
#define D_K    64
#define NB     64
#define HID_DIM 256
#define OUT_DIM 10

// Scratch (static device globals; allocation is forbidden).
__device__ __align__(16) __half g_H[NNODES * D_H];     // fp16 features
__device__ __align__(16) __half g_AGG[NNODES * D_H];   // fp16 aggregation
__device__ __align__(16) __half g_Xh[NNODES * D_IN];   // fp16 copy of x
__device__ __align__(16) __half g_Wt[D_H * D_H];       // Wt[n][k], k-contiguous (max K=192)
__device__ float g_bias[D_H];                          // concatenated bias
__device__ float g_POOL[NB * D_H];
__device__ float g_HID[NB * HID_DIM];

// ---------------------------------------------------------------------------
// Zero-fill helpers
// ---------------------------------------------------------------------------
__global__ void zero_agg_kernel() {
    const int i = blockIdx.x * blockDim.x + threadIdx.x;
    const int nvec = NNODES * D_H / 8;
    if (i < nvec)
        reinterpret_cast<uint4*>(g_AGG)[i] = make_uint4(0u, 0u, 0u, 0u);
}

__global__ void zero_pool_kernel() {
    const int i = blockIdx.x * blockDim.x + threadIdx.x;
    if (i < NB * D_H) g_POOL[i] = 0.f;
}

// ---------------------------------------------------------------------------
// Conversions (run per launch; deterministic)
// ---------------------------------------------------------------------------
__global__ void convert_x_kernel(const float* __restrict__ x) {
    const int i = blockIdx.x * blockDim.x + threadIdx.x;
    if (i < NNODES * D_IN / 4) {
        float4 v = reinterpret_cast<const float4*>(x)[i];
        __half2* o = reinterpret_cast<__half2*>(g_Xh) + i * 2;
        o[0] = __floats2half2_rn(v.x, v.y);
        o[1] = __floats2half2_rn(v.z, v.w);
    }
}

// Build Wt[n][k] = W_{n/64}[k][n%64] (fp16) and g_bias[n] (fp32).
template <int K>
__global__ void convert_w_kernel(
    const float* __restrict__ W0, const float* __restrict__ b0,
    const float* __restrict__ W1, const float* __restrict__ b1,
    const float* __restrict__ W2, const float* __restrict__ b2)
{
    const int i = blockIdx.x * blockDim.x + threadIdx.x;
    if (i < D_H * K) {
        int n = i / K, k = i % K;
        const float* __restrict__ W = (n < 64) ? W0 : ((n < 128) ? W1 : W2);
        g_Wt[i] = __float2half(W[k * D_K + (n & 63)]);
    }
    if (i < D_H) {
        const float* __restrict__ bb = (i < 64) ? b0 : ((i < 128) ? b1 : b2);
        g_bias[i] = bb[i & 63];
    }
}

// ---------------------------------------------------------------------------
// Tensor-core concat-GEMM: g_H[n, 0:192] = relu?(in[n,:]) @ Wt^T + bias (fp16)
// 256 threads = 8 warps in a 2(m) x 4(n) grid. Block tile: 32 nodes x 192 cols.
// Each warp: m16 x n48 (6 n8-tiles), fp32 accum, K in k16 steps.
// SRC=0: input g_Xh. SRC=1: input g_AGG with relu folded into staging.
// ---------------------------------------------------------------------------
__device__ __forceinline__ void mma_16816(
    float& c0, float& c1, float& c2, float& c3,
    uint32_t a0, uint32_t a1, uint32_t a2, uint32_t a3,
    uint32_t b0, uint32_t b1)
{
    asm volatile(
        "mma.sync.aligned.m16n8k16.row.col.f32.f16.f16.f32 "
        "{%0,%1,%2,%3}, {%4,%5,%6,%7}, {%8,%9}, {%0,%1,%2,%3};"
        : "+f"(c0), "+f"(c1), "+f"(c2), "+f"(c3)
        : "r"(a0), "r"(a1), "r"(a2), "r"(a3), "r"(b0), "r"(b1));
}

template <int K, int SRC>
__global__ void __launch_bounds__(256) mma_gemm_kernel()
{
    constexpr int BM = 32;
    constexpr int KP = K + 8;                       // padded row (halves)
    __shared__ __align__(16) __half As[BM * KP];

    const int tid   = threadIdx.x;
    const int node0 = blockIdx.x * BM;

    // ---- stage A tile (fp16) into smem, zero-fill OOR rows ----
    {
        constexpr int C8 = K / 8;                   // uint4 chunks per row
        const uint4 zero = make_uint4(0u, 0u, 0u, 0u);
        for (int idx = tid; idx < BM * C8; idx += 256) {
            int row = idx / C8, c8 = idx % C8;
            int gn  = node0 + row;
            uint4 v = zero;
            if (gn < NNODES) {
                if (SRC == 0) {
                    v = *reinterpret_cast<const uint4*>(
                        g_Xh + (size_t)gn * K + c8 * 8);
                } else {
                    v = *reinterpret_cast<const uint4*>(
                        g_AGG + (size_t)gn * K + c8 * 8);
                    __half2* h2 = reinterpret_cast<__half2*>(&v);
                    const __half2 z2 = __float2half2_rn(0.f);
#pragma unroll
                    for (int j = 0; j < 4; j++) h2[j] = __hmax2(h2[j], z2);
                }
            }
            *reinterpret_cast<uint4*>(&As[row * KP + c8 * 8]) = v;
        }
    }
    __syncthreads();

    const int wid  = tid >> 5, lane = tid & 31;
    const int wm   = wid >> 2;                      // 0..1 (m warp)
    const int wn   = wid & 3;                       // 0..3 (n warp)
    const int m0   = wm * 16;
    const int n0   = wn * 48;
    const int gid  = lane >> 2, tig = lane & 3;

    float c[6][4];
#pragma unroll
    for (int t = 0; t < 6; t++)
#pragma unroll
        for (int j = 0; j < 4; j++) c[t][j] = 0.f;

    const int ar0 = (m0 + gid) * KP;
    const int ar1 = (m0 + gid + 8) * KP;

#pragma unroll
    for (int k0 = 0; k0 < K; k0 += 16) {
        const int ka = k0 + tig * 2;
        uint32_t a0 = *reinterpret_cast<const uint32_t*>(&As[ar0 + ka]);
        uint32_t a1 = *reinterpret_cast<const uint32_t*>(&As[ar1 + ka]);
        uint32_t a2 = *reinterpret_cast<const uint32_t*>(&As[ar0 + ka + 8]);
        uint32_t a3 = *reinterpret_cast<const uint32_t*>(&As[ar1 + ka + 8]);
#pragma unroll
        for (int t = 0; t < 6; t++) {
            const int n = n0 + t * 8 + gid;         // B column
            uint32_t b0 = *reinterpret_cast<const uint32_t*>(&g_Wt[n * K + ka]);
            uint32_t b1 = *reinterpret_cast<const uint32_t*>(&g_Wt[n * K + ka + 8]);
            mma_16816(c[t][0], c[t][1], c[t][2], c[t][3], a0, a1, a2, a3, b0, b1);
        }
    }

    // ---- epilogue: bias + fp16 pack + store ----
    const int r0 = node0 + m0 + gid;
    const int r1 = r0 + 8;
#pragma unroll
    for (int t = 0; t < 6; t++) {
        const int colp = n0 + t * 8 + tig * 2;
        float2 bias = *reinterpret_cast<const float2*>(&g_bias[colp]);
        if (r0 < NNODES) {
            *reinterpret_cast<__half2*>(g_H + (size_t)r0 * D_H + colp) =
                __floats2half2_rn(c[t][0] + bias.x, c[t][1] + bias.y);
        }
        if (r1 < NNODES) {
            *reinterpret_cast<__half2*>(g_H + (size_t)r1 * D_H + colp) =
                __floats2half2_rn(c[t][2] + bias.x, c[t][3] + bias.y);
        }
    }
}

// ---------------------------------------------------------------------------
// Edge scatter: AGG[dst, coff:coff+64] += H[src, coff:coff+64]   (fp16)
// 8 threads per edge; one red.global.add.noftz.v4.f16x2 each (8 halves).
// ---------------------------------------------------------------------------
__device__ __forceinline__ void red_add_v4_f16x2(__half* p, uint4 v) {
    asm volatile("red.global.add.noftz.v4.f16x2 [%0], {%1, %2, %3, %4};"
                 :: "l"(p), "r"(v.x), "r"(v.y), "r"(v.z), "r"(v.w)
                 : "memory");
}

__global__ void __launch_bounds__(256) scatter_kernel(
    const int* __restrict__ m0, const int* __restrict__ m1,
    const int* __restrict__ m2)
{
    const int* __restrict__ m =
        (blockIdx.y == 0) ? m0 : (blockIdx.y == 1 ? m1 : m2);
    const int coff = blockIdx.y * D_K;

    const int tid = threadIdx.x;
    const int e   = blockIdx.x * 32 + (tid >> 3);
    const int l   = tid & 7;
    if (e >= NEDGES) return;

    const int dst = m[e];
    const int src = m[NEDGES + e];

    const uint4 v = *reinterpret_cast<const uint4*>(
        g_H + (size_t)src * D_H + coff + l * 8);
    red_add_v4_f16x2(g_AGG + (size_t)dst * D_H + coff + l * 8, v);
}

// ---------------------------------------------------------------------------
// Pooling: POOL[batch_idx[n], c] += relu(AGG[n, c]).  (sorted batch_idx)
// ---------------------------------------------------------------------------
__global__ void __launch_bounds__(192) pool_kernel(
    const int* __restrict__ batch_idx)
{
    constexpr int CHUNK = 128;
    __shared__ int sb[CHUNK];

    const int tid   = threadIdx.x;
    const int node0 = blockIdx.x * CHUNK;

    for (int j = tid; j < CHUNK; j += 192) {
        int n = node0 + j;
        sb[j] = (n < NNODES) ? batch_idx[n] : -1;
    }
    __syncthreads();

    int   cur = -1;
    float acc = 0.f;
    for (int j = 0; j < CHUNK; j++) {
        int b = sb[j];
        if (b < 0) break;
        if (b != cur) {
            if (cur >= 0) atomicAdd(&g_POOL[cur * D_H + tid], acc);
            cur = b;
            acc = 0.f;
        }
        float v = __half2float(g_AGG[(size_t)(node0 + j) * D_H + tid]);
        acc += fmaxf(v, 0.f);
    }
    if (cur >= 0) atomicAdd(&g_POOL[cur * D_H + tid], acc);
}

// ---------------------------------------------------------------------------
// MLP head
// ---------------------------------------------------------------------------
__global__ void __launch_bounds__(HID_DIM) mlp1_kernel(
    const float* __restrict__ A1, const float* __restrict__ ba1)
{
    __shared__ float sp[D_H];
    const int b = blockIdx.x;
    const int t = threadIdx.x;
    for (int k = t; k < D_H; k += HID_DIM) sp[k] = g_POOL[b * D_H + k];
    __syncthreads();

    float acc = ba1[t];
    for (int k = 0; k < D_H; k++) acc += sp[k] * A1[k * HID_DIM + t];
    g_HID[b * HID_DIM + t] = fmaxf(acc, 0.f);
}

__global__ void __launch_bounds__(NB * OUT_DIM) mlp2_kernel(
    const float* __restrict__ A2, const float* __restrict__ ba2,
    float* __restrict__ OUT)
{
    const int t = threadIdx.x;
    const int b = t / OUT_DIM;
    const int o = t % OUT_DIM;
    float acc = ba2[o];
    for (int k = 0; k < HID_DIM; k++)
        acc += g_HID[b * HID_DIM + k] * A2[k * OUT_DIM + o];
    OUT[b * OUT_DIM + o] = acc;
}

// ---------------------------------------------------------------------------
extern "C" void kernel_launch(void* const* d_in, const int* in_sizes, int n_in,
                              void* d_out, int out_size)
{
    const float* x         = (const float*)d_in[0];
    const int*   map00     = (const int*)d_in[1];
    const int*   map01     = (const int*)d_in[2];
    const int*   map02     = (const int*)d_in[3];
    const int*   map10     = (const int*)d_in[4];
    const int*   map11     = (const int*)d_in[5];
    const int*   map12     = (const int*)d_in[6];
    const int*   batch_idx = (const int*)d_in[7];
    // d_in[8] = batch_size (compile-time NB)
    const float* W00 = (const float*)d_in[9];
    const float* b00 = (const float*)d_in[10];
    const float* W01 = (const float*)d_in[11];
    const float* b01 = (const float*)d_in[12];
    const float* W02 = (const float*)d_in[13];
    const float* b02 = (const float*)d_in[14];
    const float* W10 = (const float*)d_in[15];
    const float* b10 = (const float*)d_in[16];
    const float* W11 = (const float*)d_in[17];
    const float* b11 = (const float*)d_in[18];
    const float* W12 = (const float*)d_in[19];
    const float* b12 = (const float*)d_in[20];
    const float* A1  = (const float*)d_in[21];
    const float* ba1 = (const float*)d_in[22];
    const float* A2  = (const float*)d_in[23];
    const float* ba2 = (const float*)d_in[24];
    float* out = (float*)d_out;

    const int gemm_blocks    = (NNODES + 31) / 32;
    const int scatter_blocks = (NEDGES + 31) / 32;
    const int pool_blocks    = (NNODES + 127) / 128;
    const int zero_blocks    = (NNODES * D_H / 8 + 255) / 256;
    const int convx_blocks   = (NNODES * D_IN / 4 + 255) / 256;
    const int convw_blocks   = (D_H * D_H + 255) / 256;

    // ---- layer 0 ----
    convert_x_kernel<<<convx_blocks, 256>>>(x);
    convert_w_kernel<D_IN><<<convw_blocks, 256>>>(W00, b00, W01, b01, W02, b02);
    mma_gemm_kernel<D_IN, 0><<<gemm_blocks, 256>>>();
    zero_agg_kernel<<<zero_blocks, 256>>>();
    scatter_kernel<<<dim3(scatter_blocks, 3), 256>>>(map00, map01, map02);

    // ---- layer 1 ----
    convert_w_kernel<D_H><<<convw_blocks, 256>>>(W10, b10, W11, b11, W12, b12);
    mma_gemm_kernel<D_H, 1><<<gemm_blocks, 256>>>();
    zero_agg_kernel<<<zero_blocks, 256>>>();
    scatter_kernel<<<dim3(scatter_blocks, 3), 256>>>(map10, map11, map12);

    // ---- pooling ----
    zero_pool_kernel<<<(NB * D_H + 255) / 256, 256>>>();
    pool_kernel<<<pool_blocks, 192>>>(batch_idx);

    // ---- MLP head ----
    mlp1_kernel<<<NB, HID_DIM>>>(A1, ba1);
    mlp2_kernel<<<1, NB * OUT_DIM>>>(A2, ba2, out);
}

// round 9
// speedup vs baseline: 4.1545x; 1.1599x over previous
#include <cuda_runtime.h>
#include <cuda_fp16.h>
#include <cstdint>

using std::uint32_t;

#define NNODES 50000
#define NEDGES 800000
#define D_IN   128
#define D_H    192
#define D_K    64
#define NB     64
#define HID_DIM 256
#define OUT_DIM 10

// Scratch (static device globals; allocation is forbidden).
__device__ __align__(16) __half g_H[NNODES * D_H];     // fp16 features
__device__ __align__(16) __half g_AGG[NNODES * D_H];   // fp16 aggregation
__device__ __align__(16) __half g_Wt[D_H * D_H];       // Wt[n][k], k-contiguous (max K=192)
__device__ float g_bias[D_H];                          // concatenated bias
__device__ float g_POOL[NB * D_H];
__device__ float g_HID[NB * HID_DIM];

// ---------------------------------------------------------------------------
__global__ void zero_pool_kernel() {
    const int i = blockIdx.x * blockDim.x + threadIdx.x;
    if (i < NB * D_H) g_POOL[i] = 0.f;
}

// Build Wt[n][k] = W_{n/64}[k][n%64] (fp16) and g_bias[n] (fp32).
template <int K>
__global__ void convert_w_kernel(
    const float* __restrict__ W0, const float* __restrict__ b0,
    const float* __restrict__ W1, const float* __restrict__ b1,
    const float* __restrict__ W2, const float* __restrict__ b2)
{
    const int i = blockIdx.x * blockDim.x + threadIdx.x;
    if (i < D_H * K) {
        int n = i / K, k = i % K;
        const float* __restrict__ W = (n < 64) ? W0 : ((n < 128) ? W1 : W2);
        g_Wt[i] = __float2half(W[k * D_K + (n & 63)]);
    }
    if (i < D_H) {
        const float* __restrict__ bb = (i < 64) ? b0 : ((i < 128) ? b1 : b2);
        g_bias[i] = bb[i & 63];
    }
}

// ---------------------------------------------------------------------------
// Tensor-core concat-GEMM: g_H[n, 0:192] = relu?(in[n,:]) @ Wt^T + bias (fp16)
// 256 threads = 8 warps in a 2(m) x 4(n) grid. Block tile: 64 nodes x 192 cols.
// Warp tile: m32 x n48 (2 m16-tiles x 6 n8-tiles), fp32 accum.
// SRC=0: fp32 X input (converted in staging). SRC=1: g_AGG with fused relu.
// Epilogue additionally zeroes this block's rows of g_AGG (block-local; safe).
// ---------------------------------------------------------------------------
__device__ __forceinline__ void mma_16816(
    float& c0, float& c1, float& c2, float& c3,
    uint32_t a0, uint32_t a1, uint32_t a2, uint32_t a3,
    uint32_t b0, uint32_t b1)
{
    asm volatile(
        "mma.sync.aligned.m16n8k16.row.col.f32.f16.f16.f32 "
        "{%0,%1,%2,%3}, {%4,%5,%6,%7}, {%8,%9}, {%0,%1,%2,%3};"
        : "+f"(c0), "+f"(c1), "+f"(c2), "+f"(c3)
        : "r"(a0), "r"(a1), "r"(a2), "r"(a3), "r"(b0), "r"(b1));
}

template <int K, int SRC>
__global__ void __launch_bounds__(256) mma_gemm_kernel(const float* __restrict__ X)
{
    constexpr int BM = 64;
    constexpr int KP = K + 8;                       // padded row (halves)
    __shared__ __align__(16) __half As[BM * KP];

    const int tid   = threadIdx.x;
    const int node0 = blockIdx.x * BM;

    // ---- stage A tile (fp16) into smem, zero-fill OOR rows ----
    {
        constexpr int C8 = K / 8;                   // 8-half chunks per row
        for (int idx = tid; idx < BM * C8; idx += 256) {
            int row = idx / C8, c8 = idx % C8;
            int gn  = node0 + row;
            uint4 v = make_uint4(0u, 0u, 0u, 0u);
            if (gn < NNODES) {
                if (SRC == 0) {
                    // fp32 -> fp16 conversion fused into staging
                    const float4 f0 = *reinterpret_cast<const float4*>(
                        X + (size_t)gn * K + c8 * 8);
                    const float4 f1 = *reinterpret_cast<const float4*>(
                        X + (size_t)gn * K + c8 * 8 + 4);
                    __half2* h2 = reinterpret_cast<__half2*>(&v);
                    h2[0] = __floats2half2_rn(f0.x, f0.y);
                    h2[1] = __floats2half2_rn(f0.z, f0.w);
                    h2[2] = __floats2half2_rn(f1.x, f1.y);
                    h2[3] = __floats2half2_rn(f1.z, f1.w);
                } else {
                    v = *reinterpret_cast<const uint4*>(
                        g_AGG + (size_t)gn * K + c8 * 8);
                    __half2* h2 = reinterpret_cast<__half2*>(&v);
                    const __half2 z2 = __float2half2_rn(0.f);
#pragma unroll
                    for (int j = 0; j < 4; j++) h2[j] = __hmax2(h2[j], z2);
                }
            }
            *reinterpret_cast<uint4*>(&As[row * KP + c8 * 8]) = v;
        }
    }
    __syncthreads();

    // ---- zero this block's AGG rows (staging reads are done) ----
    {
        constexpr int CZ = D_H / 8;                 // 24 chunks per row
        const uint4 zero = make_uint4(0u, 0u, 0u, 0u);
        for (int idx = tid; idx < BM * CZ; idx += 256) {
            int row = idx / CZ, c8 = idx % CZ;
            int gn  = node0 + row;
            if (gn < NNODES)
                *reinterpret_cast<uint4*>(
                    g_AGG + (size_t)gn * D_H + c8 * 8) = zero;
        }
    }

    const int wid  = tid >> 5, lane = tid & 31;
    const int wm   = wid >> 2;                      // 0..1 (m warp)
    const int wn   = wid & 3;                       // 0..3 (n warp)
    const int m0   = wm * 32;
    const int n0   = wn * 48;
    const int gid  = lane >> 2, tig = lane & 3;

    float c[2][6][4];
#pragma unroll
    for (int mt = 0; mt < 2; mt++)
#pragma unroll
        for (int t = 0; t < 6; t++)
#pragma unroll
            for (int j = 0; j < 4; j++) c[mt][t][j] = 0.f;

#pragma unroll
    for (int k0 = 0; k0 < K; k0 += 16) {
        const int ka = k0 + tig * 2;
        uint32_t a[2][4];
#pragma unroll
        for (int mt = 0; mt < 2; mt++) {
            const int ar0 = (m0 + mt * 16 + gid) * KP;
            const int ar1 = ar0 + 8 * KP;
            a[mt][0] = *reinterpret_cast<const uint32_t*>(&As[ar0 + ka]);
            a[mt][1] = *reinterpret_cast<const uint32_t*>(&As[ar1 + ka]);
            a[mt][2] = *reinterpret_cast<const uint32_t*>(&As[ar0 + ka + 8]);
            a[mt][3] = *reinterpret_cast<const uint32_t*>(&As[ar1 + ka + 8]);
        }
#pragma unroll
        for (int t = 0; t < 6; t++) {
            const int n = n0 + t * 8 + gid;         // B column
            uint32_t b0 = *reinterpret_cast<const uint32_t*>(&g_Wt[n * K + ka]);
            uint32_t b1 = *reinterpret_cast<const uint32_t*>(&g_Wt[n * K + ka + 8]);
#pragma unroll
            for (int mt = 0; mt < 2; mt++)
                mma_16816(c[mt][t][0], c[mt][t][1], c[mt][t][2], c[mt][t][3],
                          a[mt][0], a[mt][1], a[mt][2], a[mt][3], b0, b1);
        }
    }

    // ---- epilogue: bias + fp16 pack + store ----
#pragma unroll
    for (int mt = 0; mt < 2; mt++) {
        const int r0 = node0 + m0 + mt * 16 + gid;
        const int r1 = r0 + 8;
#pragma unroll
        for (int t = 0; t < 6; t++) {
            const int colp = n0 + t * 8 + tig * 2;
            float2 bias = *reinterpret_cast<const float2*>(&g_bias[colp]);
            if (r0 < NNODES) {
                *reinterpret_cast<__half2*>(g_H + (size_t)r0 * D_H + colp) =
                    __floats2half2_rn(c[mt][t][0] + bias.x, c[mt][t][1] + bias.y);
            }
            if (r1 < NNODES) {
                *reinterpret_cast<__half2*>(g_H + (size_t)r1 * D_H + colp) =
                    __floats2half2_rn(c[mt][t][2] + bias.x, c[mt][t][3] + bias.y);
            }
        }
    }
}

// ---------------------------------------------------------------------------
// Edge scatter: AGG[dst, coff:coff+64] += H[src, coff:coff+64]   (fp16)
// 8 threads per edge; one red.global.add.noftz.v4.f16x2 each (8 halves).
// ---------------------------------------------------------------------------
__device__ __forceinline__ void red_add_v4_f16x2(__half* p, uint4 v) {
    asm volatile("red.global.add.noftz.v4.f16x2 [%0], {%1, %2, %3, %4};"
                 :: "l"(p), "r"(v.x), "r"(v.y), "r"(v.z), "r"(v.w)
                 : "memory");
}

__global__ void __launch_bounds__(256) scatter_kernel(
    const int* __restrict__ m0, const int* __restrict__ m1,
    const int* __restrict__ m2)
{
    const int* __restrict__ m =
        (blockIdx.y == 0) ? m0 : (blockIdx.y == 1 ? m1 : m2);
    const int coff = blockIdx.y * D_K;

    const int tid = threadIdx.x;
    const int e   = blockIdx.x * 32 + (tid >> 3);
    const int l   = tid & 7;
    if (e >= NEDGES) return;

    const int dst = m[e];
    const int src = m[NEDGES + e];

    const uint4 v = *reinterpret_cast<const uint4*>(
        g_H + (size_t)src * D_H + coff + l * 8);
    red_add_v4_f16x2(g_AGG + (size_t)dst * D_H + coff + l * 8, v);
}

// ---------------------------------------------------------------------------
// Pooling: POOL[batch_idx[n], c] += relu(AGG[n, c]).  (sorted batch_idx)
// ---------------------------------------------------------------------------
__global__ void __launch_bounds__(192) pool_kernel(
    const int* __restrict__ batch_idx)
{
    constexpr int CHUNK = 128;
    __shared__ int sb[CHUNK];

    const int tid   = threadIdx.x;
    const int node0 = blockIdx.x * CHUNK;

    for (int j = tid; j < CHUNK; j += 192) {
        int n = node0 + j;
        sb[j] = (n < NNODES) ? batch_idx[n] : -1;
    }
    __syncthreads();

    int   cur = -1;
    float acc = 0.f;
    for (int j = 0; j < CHUNK; j++) {
        int b = sb[j];
        if (b < 0) break;
        if (b != cur) {
            if (cur >= 0) atomicAdd(&g_POOL[cur * D_H + tid], acc);
            cur = b;
            acc = 0.f;
        }
        float v = __half2float(g_AGG[(size_t)(node0 + j) * D_H + tid]);
        acc += fmaxf(v, 0.f);
    }
    if (cur >= 0) atomicAdd(&g_POOL[cur * D_H + tid], acc);
}

// ---------------------------------------------------------------------------
// MLP head
// ---------------------------------------------------------------------------
__global__ void __launch_bounds__(HID_DIM) mlp1_kernel(
    const float* __restrict__ A1, const float* __restrict__ ba1)
{
    __shared__ float sp[D_H];
    const int b = blockIdx.x;
    const int t = threadIdx.x;
    for (int k = t; k < D_H; k += HID_DIM) sp[k] = g_POOL[b * D_H + k];
    __syncthreads();

    float acc = ba1[t];
    for (int k = 0; k < D_H; k++) acc += sp[k] * A1[k * HID_DIM + t];
    g_HID[b * HID_DIM + t] = fmaxf(acc, 0.f);
}

__global__ void __launch_bounds__(NB * OUT_DIM) mlp2_kernel(
    const float* __restrict__ A2, const float* __restrict__ ba2,
    float* __restrict__ OUT)
{
    const int t = threadIdx.x;
    const int b = t / OUT_DIM;
    const int o = t % OUT_DIM;
    float acc = ba2[o];
    for (int k = 0; k < HID_DIM; k++)
        acc += g_HID[b * HID_DIM + k] * A2[k * OUT_DIM + o];
    OUT[b * OUT_DIM + o] = acc;
}

// ---------------------------------------------------------------------------
extern "C" void kernel_launch(void* const* d_in, const int* in_sizes, int n_in,
                              void* d_out, int out_size)
{
    const float* x         = (const float*)d_in[0];
    const int*   map00     = (const int*)d_in[1];
    const int*   map01     = (const int*)d_in[2];
    const int*   map02     = (const int*)d_in[3];
    const int*   map10     = (const int*)d_in[4];
    const int*   map11     = (const int*)d_in[5];
    const int*   map12     = (const int*)d_in[6];
    const int*   batch_idx = (const int*)d_in[7];
    // d_in[8] = batch_size (compile-time NB)
    const float* W00 = (const float*)d_in[9];
    const float* b00 = (const float*)d_in[10];
    const float* W01 = (const float*)d_in[11];
    const float* b01 = (const float*)d_in[12];
    const float* W02 = (const float*)d_in[13];
    const float* b02 = (const float*)d_in[14];
    const float* W10 = (const float*)d_in[15];
    const float* b10 = (const float*)d_in[16];
    const float* W11 = (const float*)d_in[17];
    const float* b11 = (const float*)d_in[18];
    const float* W12 = (const float*)d_in[19];
    const float* b12 = (const float*)d_in[20];
    const float* A1  = (const float*)d_in[21];
    const float* ba1 = (const float*)d_in[22];
    const float* A2  = (const float*)d_in[23];
    const float* ba2 = (const float*)d_in[24];
    float* out = (float*)d_out;

    const int gemm_blocks    = (NNODES + 63) / 64;
    const int scatter_blocks = (NEDGES + 31) / 32;
    const int pool_blocks    = (NNODES + 127) / 128;
    const int convw_blocks   = (D_H * D_H + 255) / 256;

    // ---- layer 0 (AGG zeroing fused into GEMM epilogue) ----
    convert_w_kernel<D_IN><<<convw_blocks, 256>>>(W00, b00, W01, b01, W02, b02);
    mma_gemm_kernel<D_IN, 0><<<gemm_blocks, 256>>>(x);
    scatter_kernel<<<dim3(scatter_blocks, 3), 256>>>(map00, map01, map02);

    // ---- layer 1 ----
    convert_w_kernel<D_H><<<convw_blocks, 256>>>(W10, b10, W11, b11, W12, b12);
    mma_gemm_kernel<D_H, 1><<<gemm_blocks, 256>>>(nullptr);
    scatter_kernel<<<dim3(scatter_blocks, 3), 256>>>(map10, map11, map12);

    // ---- pooling ----
    zero_pool_kernel<<<(NB * D_H + 255) / 256, 256>>>();
    pool_kernel<<<pool_blocks, 192>>>(batch_idx);

    // ---- MLP head ----
    mlp1_kernel<<<NB, HID_DIM>>>(A1, ba1);
    mlp2_kernel<<<1, NB * OUT_DIM>>>(A2, ba2, out);
}